// round 1
// baseline (speedup 1.0000x reference)
#include <cuda_runtime.h>
#include <math.h>

#define BATCH 8
#define NTOK  2048
#define FDIM  64
#define ALPHA 0.2f
#define JT    128   // j-tile (static smem <= 48KB)

// Scratch (allocation-free rule: __device__ globals)
__device__ __align__(16) float g_Wh[BATCH * NTOK * FDIM];
__device__ float g_ssrc[BATCH * NTOK];
__device__ float g_sdst[BATCH * NTOK];
__device__ float g_u[BATCH * NTOK];
__device__ float g_v[BATCH * NTOK];
__device__ float g_maxs[BATCH];

__device__ __forceinline__ float eluf(float x) { return x > 0.f ? x : expm1f(x); }

// ---------------------------------------------------------------------------
// Kernel 1: Wh = h @ W ; s_src, s_dst, u=exp(s_dst), v=exp(a*s_dst) per row
// ---------------------------------------------------------------------------
__global__ void k1_proj(const float* __restrict__ h,
                        const float* __restrict__ W,
                        const float* __restrict__ a) {
    __shared__ float W_s[64 * 64];
    __shared__ float a_s[128];
    __shared__ float h_s[32 * 64];
    int tid = threadIdx.x;
    for (int i = tid; i < 64 * 64; i += 256) W_s[i] = W[i];
    if (tid < 128) a_s[tid] = a[tid];
    int row0 = blockIdx.x * 32;
    for (int i = tid; i < 32 * 64; i += 256) h_s[i] = h[row0 * 64 + i];
    __syncthreads();

    int warp = tid >> 5, lane = tid & 31;
    for (int r = warp; r < 32; r += 8) {
        int row = row0 + r;
        float wh0 = 0.f, wh1 = 0.f;
#pragma unroll
        for (int k = 0; k < 64; k++) {
            float hk = h_s[r * 64 + k];
            wh0 = fmaf(hk, W_s[k * 64 + lane], wh0);
            wh1 = fmaf(hk, W_s[k * 64 + lane + 32], wh1);
        }
        g_Wh[row * 64 + lane]      = wh0;
        g_Wh[row * 64 + lane + 32] = wh1;
        float ps = wh0 * a_s[lane] + wh1 * a_s[lane + 32];
        float pd = wh0 * a_s[64 + lane] + wh1 * a_s[64 + lane + 32];
#pragma unroll
        for (int o = 16; o > 0; o >>= 1) {
            ps += __shfl_xor_sync(0xffffffffu, ps, o);
            pd += __shfl_xor_sync(0xffffffffu, pd, o);
        }
        if (lane == 0) {
            g_ssrc[row] = ps;
            g_sdst[row] = pd;
            g_u[row] = expf(pd);
            g_v[row] = expf(ALPHA * pd);
        }
    }
}

// ---------------------------------------------------------------------------
// Kernel 2: per-batch max of s_dst (for stable softmax shift; leaky monotone)
// ---------------------------------------------------------------------------
__global__ void k2_max() {
    int b = blockIdx.x, tid = threadIdx.x;
    float m = -1e30f;
    for (int j = tid; j < NTOK; j += 256) m = fmaxf(m, g_sdst[b * NTOK + j]);
    __shared__ float red[256];
    red[tid] = m;
    __syncthreads();
    for (int s = 128; s > 0; s >>= 1) {
        if (tid < s) red[tid] = fmaxf(red[tid], red[tid + s]);
        __syncthreads();
    }
    if (tid == 0) g_maxs[b] = red[0];
}

// ---------------------------------------------------------------------------
// Kernel 3: fused  out = elu( softmax(leaky(s_src_i+s_dst_j)) @ Wh )
//   p_ij = exp(e_ij - m_i) = (t>0) ? A_i*u_j : B_i*v_j   (NO exp in loop)
//   Block: 256 thr = 8 warps, 8 i-rows/warp (I_TILE=64).
//   Warp: 4 quarter-groups each take one j; lane handles 8 o's
//   (o = 4*ol..+3 and 32+4*ol..+3) -> conflict-free LDS.128.
// ---------------------------------------------------------------------------
__global__ void __launch_bounds__(256) k3_attn(float* __restrict__ out) {
    __shared__ __align__(16) float Wh_s[JT * 64];
    __shared__ float sd_s[JT], u_s[JT], v_s[JT];

    int b = blockIdx.y;
    int tid = threadIdx.x;
    int warp = tid >> 5, lane = tid & 31;
    int jg = lane >> 3, ol = lane & 7;
    int i0 = blockIdx.x * 64 + warp * 8;

    float M = g_maxs[b];
    float ssr[8], Ai[8], Bi[8];
#pragma unroll
    for (int i = 0; i < 8; i++) {
        float s = g_ssrc[b * NTOK + i0 + i];
        float t = s + M;
        float m = t > 0.f ? t : ALPHA * t;
        ssr[i] = s;
        Ai[i] = expf(s - m);
        Bi[i] = expf(ALPHA * s - m);
    }

    float acc[8][8], zz[8];
#pragma unroll
    for (int i = 0; i < 8; i++) {
        zz[i] = 0.f;
#pragma unroll
        for (int o = 0; o < 8; o++) acc[i][o] = 0.f;
    }

    const float* Whb = g_Wh + b * NTOK * 64;

    for (int jt = 0; jt < NTOK; jt += JT) {
        __syncthreads();
        const float4* src = (const float4*)(Whb + jt * 64);
        float4* dst = (float4*)Wh_s;
        for (int idx = tid; idx < JT * 16; idx += 256) dst[idx] = src[idx];
        for (int idx = tid; idx < JT; idx += 256) {
            sd_s[idx] = g_sdst[b * NTOK + jt + idx];
            u_s[idx]  = g_u[b * NTOK + jt + idx];
            v_s[idx]  = g_v[b * NTOK + jt + idx];
        }
        __syncthreads();

        for (int jj = 0; jj < JT; jj += 4) {
            int j = jj + jg;
            float sdj = sd_s[j];
            float uj = u_s[j];
            float vj = v_s[j];
            float4 wa = *(const float4*)&Wh_s[j * 64 + 4 * ol];
            float4 wb = *(const float4*)&Wh_s[j * 64 + 32 + 4 * ol];
#pragma unroll
            for (int i = 0; i < 8; i++) {
                float t = ssr[i] + sdj;
                float p = (t > 0.f) ? (Ai[i] * uj) : (Bi[i] * vj);
                zz[i] += p;
                acc[i][0] = fmaf(p, wa.x, acc[i][0]);
                acc[i][1] = fmaf(p, wa.y, acc[i][1]);
                acc[i][2] = fmaf(p, wa.z, acc[i][2]);
                acc[i][3] = fmaf(p, wa.w, acc[i][3]);
                acc[i][4] = fmaf(p, wb.x, acc[i][4]);
                acc[i][5] = fmaf(p, wb.y, acc[i][5]);
                acc[i][6] = fmaf(p, wb.z, acc[i][6]);
                acc[i][7] = fmaf(p, wb.w, acc[i][7]);
            }
        }
    }

    // combine the 4 j-groups' partials (lanes l, l+8, l+16, l+24 share o's)
#pragma unroll
    for (int i = 0; i < 8; i++) {
#pragma unroll
        for (int o = 0; o < 8; o++) {
            acc[i][o] += __shfl_xor_sync(0xffffffffu, acc[i][o], 8);
            acc[i][o] += __shfl_xor_sync(0xffffffffu, acc[i][o], 16);
        }
        zz[i] += __shfl_xor_sync(0xffffffffu, zz[i], 8);
        zz[i] += __shfl_xor_sync(0xffffffffu, zz[i], 16);
    }

    // write: jg==0 writes o=[4ol,4ol+4), jg==1 writes o=[32+4ol,32+4ol+4)
#pragma unroll
    for (int i = 0; i < 8; i++) {
        float inv = 1.f / zz[i];
        long base = (long)(b * NTOK + i0 + i) * 64;
        if (jg == 0) {
            float4 r;
            r.x = eluf(acc[i][0] * inv);
            r.y = eluf(acc[i][1] * inv);
            r.z = eluf(acc[i][2] * inv);
            r.w = eluf(acc[i][3] * inv);
            *(float4*)&out[base + 4 * ol] = r;
        } else if (jg == 1) {
            float4 r;
            r.x = eluf(acc[i][4] * inv);
            r.y = eluf(acc[i][5] * inv);
            r.z = eluf(acc[i][6] * inv);
            r.w = eluf(acc[i][7] * inv);
            *(float4*)&out[base + 32 + 4 * ol] = r;
        }
    }
}

// ---------------------------------------------------------------------------
extern "C" void kernel_launch(void* const* d_in, const int* in_sizes, int n_in,
                              void* d_out, int out_size) {
    const float* h = (const float*)d_in[0];
    const float* W = (const float*)d_in[1];
    const float* a = (const float*)d_in[2];
    float* out = (float*)d_out;

    k1_proj<<<(BATCH * NTOK) / 32, 256>>>(h, W, a);
    k2_max<<<BATCH, 256>>>();
    dim3 g3(NTOK / 64, BATCH);
    k3_attn<<<g3, 256>>>(out);
}

// round 3
// speedup vs baseline: 2.3466x; 2.3466x over previous
#include <cuda_runtime.h>
#include <math.h>
#include <stdint.h>

#define BATCH 8
#define NTOK  2048
#define FDIM  64
#define ALPHA 0.2f

// ---------------- scratch (__device__ globals; no allocs allowed) ----------
__device__ __align__(16) float g_Wh[BATCH * NTOK * FDIM];     // [b][j][o]
__device__ __align__(16) float4 g_suv[BATCH * NTOK];          // {sd, e^sd, e^(a*sd), 0}
__device__ float g_ssrc[BATCH * NTOK];
__device__ float g_maxs[BATCH];

__device__ __forceinline__ float eluf(float x) { return x > 0.f ? x : expm1f(x); }

__device__ __forceinline__ uint32_t cvt_tf32(float x) {
    uint32_t r;
    asm("cvt.rna.tf32.f32 %0, %1;" : "=r"(r) : "f"(x));
    return r;
}

__device__ __forceinline__ void mma_tf32(float* d, uint32_t a0, uint32_t a1,
                                         uint32_t a2, uint32_t a3,
                                         uint32_t b0, uint32_t b1) {
    asm volatile(
        "mma.sync.aligned.m16n8k8.row.col.f32.tf32.tf32.f32 "
        "{%0,%1,%2,%3}, {%4,%5,%6,%7}, {%8,%9}, {%0,%1,%2,%3};"
        : "+f"(d[0]), "+f"(d[1]), "+f"(d[2]), "+f"(d[3])
        : "r"(a0), "r"(a1), "r"(a2), "r"(a3), "r"(b0), "r"(b1));
}

// ---------------------------------------------------------------------------
// Kernel 1: Wh = h @ W (row-major), scores; packed suv output.
// 512 threads, 64 rows/block; thread = (row r, eighth e) -> 8 outputs.
// ---------------------------------------------------------------------------
__global__ void __launch_bounds__(512) k1_proj(const float* __restrict__ h,
                                               const float* __restrict__ W,
                                               const float* __restrict__ a) {
    __shared__ float W_s[64 * 64];
    __shared__ float a_s[128];
    __shared__ float h_s[64 * 64];

    int tid = threadIdx.x;
    int row0 = blockIdx.x * 64;
    for (int i = tid; i < 4096; i += 512) W_s[i] = W[i];
    if (tid < 128) a_s[tid] = a[tid];
    for (int i = tid; i < 4096; i += 512) h_s[i] = h[row0 * 64 + i];
    __syncthreads();

    int r = tid >> 3, e = tid & 7;
    float acc[8];
#pragma unroll
    for (int i = 0; i < 8; i++) acc[i] = 0.f;
    const float* hr = h_s + r * 64;
#pragma unroll
    for (int k = 0; k < 64; k++) {
        float hv = hr[k];
        float4 w0 = *(const float4*)&W_s[k * 64 + e * 8];
        float4 w1 = *(const float4*)&W_s[k * 64 + e * 8 + 4];
        acc[0] = fmaf(hv, w0.x, acc[0]);
        acc[1] = fmaf(hv, w0.y, acc[1]);
        acc[2] = fmaf(hv, w0.z, acc[2]);
        acc[3] = fmaf(hv, w0.w, acc[3]);
        acc[4] = fmaf(hv, w1.x, acc[4]);
        acc[5] = fmaf(hv, w1.y, acc[5]);
        acc[6] = fmaf(hv, w1.z, acc[6]);
        acc[7] = fmaf(hv, w1.w, acc[7]);
    }
    int row = row0 + r;
    // Wh store (coalesced within octet)
    float4 s0 = make_float4(acc[0], acc[1], acc[2], acc[3]);
    float4 s1 = make_float4(acc[4], acc[5], acc[6], acc[7]);
    *(float4*)&g_Wh[(size_t)row * 64 + e * 8] = s0;
    *(float4*)&g_Wh[(size_t)row * 64 + e * 8 + 4] = s1;

    float ps = 0.f, pd = 0.f;
#pragma unroll
    for (int i = 0; i < 8; i++) {
        ps = fmaf(acc[i], a_s[e * 8 + i], ps);
        pd = fmaf(acc[i], a_s[64 + e * 8 + i], pd);
    }
#pragma unroll
    for (int o = 1; o < 8; o <<= 1) {
        ps += __shfl_xor_sync(0xffffffffu, ps, o);
        pd += __shfl_xor_sync(0xffffffffu, pd, o);
    }
    if (e == 0) {
        g_ssrc[row] = ps;
        g_suv[row] = make_float4(pd, expf(pd), expf(ALPHA * pd), 0.f);
    }
}

// ---------------------------------------------------------------------------
// Kernel 2: per-batch max of s_dst (leaky monotone -> only s_dst max needed)
// ---------------------------------------------------------------------------
__global__ void k2_max() {
    int b = blockIdx.x, tid = threadIdx.x;
    float m = -1e30f;
    for (int j = tid; j < NTOK; j += 256) m = fmaxf(m, g_suv[b * NTOK + j].x);
    __shared__ float red[256];
    red[tid] = m;
    __syncthreads();
    for (int s = 128; s > 0; s >>= 1) {
        if (tid < s) red[tid] = fmaxf(red[tid], red[tid + s]);
        __syncthreads();
    }
    if (tid == 0) g_maxs[b] = red[0];
}

// ---------------------------------------------------------------------------
// Kernel 3: fused attention via mma.sync tf32 (HMMA).
//   CTA: 256 thr = 8 warps, 128 i-rows (16/warp). j loop: 16 tiles of 128.
//   A-frag (P) generated in registers, exp-free:
//     p = (ssr_i + sd_j > 0) ? Ai*u_j : Bi*v_j
//   B = Wh tile in smem, stride 72 (conflict-free), pre-cvt to tf32.
//   n-tile 8 is a ones-column -> Z lands in accumulator col 64.
// ---------------------------------------------------------------------------
#define SUV_BYTES  (NTOK * 16)
#define TILE_FLTS  (128 * 72)
#define SMEM3_TOTAL (SUV_BYTES + TILE_FLTS * 4)

__global__ void __launch_bounds__(256, 1) k3_attn(float* __restrict__ out) {
    extern __shared__ char smem[];
    float4* suv_s = (float4*)smem;                 // [2048]
    float*  T_s   = (float*)(smem + SUV_BYTES);    // [128][72]

    int tid = threadIdx.x;
    int lane = tid & 31, w = tid >> 5;
    int b = blockIdx.y;
    int i0 = blockIdx.x * 128;

    // whole-batch suv into smem
    {
        const float4* sg = g_suv + b * NTOK;
        for (int i = tid; i < NTOK; i += 256) suv_s[i] = sg[i];
    }

    int q = lane >> 2, c4 = lane & 3;
    int r0 = i0 + w * 16 + q;       // within-batch row
    int r1 = r0 + 8;
    float M = g_maxs[b];
    float ssr0 = g_ssrc[b * NTOK + r0];
    float ssr1 = g_ssrc[b * NTOK + r1];
    float t0 = ssr0 + M, t1 = ssr1 + M;
    float m0 = t0 > 0.f ? t0 : ALPHA * t0;
    float m1 = t1 > 0.f ? t1 : ALPHA * t1;
    float Ai0 = expf(ssr0 - m0), Bi0 = expf(ALPHA * ssr0 - m0);
    float Ai1 = expf(ssr1 - m1), Bi1 = expf(ALPHA * ssr1 - m1);

    float acc[9][4];
#pragma unroll
    for (int n = 0; n < 9; n++)
#pragma unroll
        for (int i = 0; i < 4; i++) acc[n][i] = 0.f;

    const float4* WhG4 = (const float4*)(g_Wh + (size_t)b * NTOK * 64);

    for (int t = 0; t < 16; t++) {
        __syncthreads();
        // ---- load Wh tile [128 j][64 o] -> T_s stride 72, cvt tf32(rna) ----
#pragma unroll
        for (int it = 0; it < 8; it++) {
            int idx = tid + it * 256;         // 0..2047
            int j = idx >> 4, o4 = idx & 15;
            float4 v = WhG4[(size_t)(t * 128 + j) * 16 + o4];
            v.x = __uint_as_float(cvt_tf32(v.x));
            v.y = __uint_as_float(cvt_tf32(v.y));
            v.z = __uint_as_float(cvt_tf32(v.z));
            v.w = __uint_as_float(cvt_tf32(v.w));
            *(float4*)&T_s[j * 72 + o4 * 4] = v;
        }
        // ones column block (cols 64..71: col 64 = 1, rest 0)
        {
            int j = tid >> 1, hf = tid & 1;
            float4 v = make_float4(hf ? 0.f : 1.f, 0.f, 0.f, 0.f);
            *(float4*)&T_s[j * 72 + 64 + hf * 4] = v;
            if (tid < 256) { /* 128 rows x 2 halves = 256 == blockDim */ }
        }
        __syncthreads();

#pragma unroll 4
        for (int c = 0; c < 16; c++) {
            int jb = t * 128 + c * 8;
            float4 s0 = suv_s[jb + c4];
            float4 s1 = suv_s[jb + c4 + 4];
            float e00 = ssr0 + s0.x, e10 = ssr1 + s0.x;
            float e01 = ssr0 + s1.x, e11 = ssr1 + s1.x;
            float p0 = (e00 > 0.f) ? Ai0 * s0.y : Bi0 * s0.z;
            float p1 = (e10 > 0.f) ? Ai1 * s0.y : Bi1 * s0.z;
            float p2 = (e01 > 0.f) ? Ai0 * s1.y : Bi0 * s1.z;
            float p3 = (e11 > 0.f) ? Ai1 * s1.y : Bi1 * s1.z;
            uint32_t a0 = cvt_tf32(p0), a1 = cvt_tf32(p1);
            uint32_t a2 = cvt_tf32(p2), a3 = cvt_tf32(p3);
            const float* bp = T_s + (c * 8 + c4) * 72 + q;
#pragma unroll
            for (int n = 0; n < 9; n++) {
                uint32_t b0 = __float_as_uint(bp[n * 8]);
                uint32_t b1 = __float_as_uint(bp[4 * 72 + n * 8]);
                mma_tf32(acc[n], a0, a1, a2, a3, b0, b1);
            }
        }
    }

    // ---- epilogue: Z from ones-column (tile 8, col 64), softmax, elu ----
    float z0 = __shfl_sync(0xffffffffu, acc[8][0], lane & 28);
    float z1 = __shfl_sync(0xffffffffu, acc[8][2], lane & 28);
    float inv0 = 1.f / z0, inv1 = 1.f / z1;

    float* o0 = out + ((size_t)(b * NTOK + r0)) * 64 + 2 * c4;
    float* o1 = out + ((size_t)(b * NTOK + r1)) * 64 + 2 * c4;
#pragma unroll
    for (int n = 0; n < 8; n++) {
        float2 wv0, wv1;
        wv0.x = eluf(acc[n][0] * inv0);
        wv0.y = eluf(acc[n][1] * inv0);
        wv1.x = eluf(acc[n][2] * inv1);
        wv1.y = eluf(acc[n][3] * inv1);
        *(float2*)(o0 + n * 8) = wv0;
        *(float2*)(o1 + n * 8) = wv1;
    }
}

// ---------------------------------------------------------------------------
extern "C" void kernel_launch(void* const* d_in, const int* in_sizes, int n_in,
                              void* d_out, int out_size) {
    const float* h = (const float*)d_in[0];
    const float* W = (const float*)d_in[1];
    const float* a = (const float*)d_in[2];
    float* out = (float*)d_out;

    cudaFuncSetAttribute(k3_attn, cudaFuncAttributeMaxDynamicSharedMemorySize,
                         SMEM3_TOTAL);

    k1_proj<<<(BATCH * NTOK) / 64, 512>>>(h, W, a);
    k2_max<<<BATCH, 256>>>();
    dim3 g3(NTOK / 128, BATCH);
    k3_attn<<<g3, 256, SMEM3_TOTAL>>>(out);
}

// round 4
// speedup vs baseline: 3.0929x; 1.3180x over previous
#include <cuda_runtime.h>
#include <math.h>
#include <stdint.h>

#define BATCH 8
#define NTOK  2048
#define FDIM  64
#define ALPHA 0.2f

// ---------------- scratch (__device__ globals; no allocs allowed) ----------
__device__ __align__(16) float g_Wh[BATCH * NTOK * FDIM];     // [b][j][o]
__device__ __align__(16) float4 g_suv[BATCH * NTOK];          // {sd, e^sd, e^(a*sd), 0}
__device__ float g_ssrc[BATCH * NTOK];
__device__ float g_maxs[BATCH];

__device__ __forceinline__ float eluf(float x) { return x > 0.f ? x : expm1f(x); }

__device__ __forceinline__ uint32_t cvt_tf32(float x) {
    uint32_t r;
    asm("cvt.rna.tf32.f32 %0, %1;" : "=r"(r) : "f"(x));
    return r;
}

__device__ __forceinline__ void mma_tf32(float* d, uint32_t a0, uint32_t a1,
                                         uint32_t a2, uint32_t a3,
                                         uint32_t b0, uint32_t b1) {
    asm volatile(
        "mma.sync.aligned.m16n8k8.row.col.f32.tf32.tf32.f32 "
        "{%0,%1,%2,%3}, {%4,%5,%6,%7}, {%8,%9}, {%0,%1,%2,%3};"
        : "+f"(d[0]), "+f"(d[1]), "+f"(d[2]), "+f"(d[3])
        : "r"(a0), "r"(a1), "r"(a2), "r"(a3), "r"(b0), "r"(b1));
}

// ---------------------------------------------------------------------------
// Kernel 1: Wh = h @ W, scores, packed suv.  128 thr, 64 rows/block,
// 4 rows/thread (g=tid>>3 picks 4 rows, e=tid&7 picks col groups e*4 & 32+e*4).
// h_s padded to 65 -> conflict-free; W col split e*4/32+e*4 -> 32-bank exact.
// ---------------------------------------------------------------------------
__global__ void __launch_bounds__(128) k1_proj(const float* __restrict__ h,
                                               const float* __restrict__ W,
                                               const float* __restrict__ a) {
    __shared__ float W_s[64 * 64];
    __shared__ float a_s[128];
    __shared__ float h_s[64 * 65];

    int tid = threadIdx.x;
    int row0 = blockIdx.x * 64;
    for (int i = tid; i < 4096; i += 128) W_s[i] = W[i];
    if (tid < 128) a_s[tid] = a[tid];
    for (int i = tid; i < 4096; i += 128) {
        int r = i >> 6, c = i & 63;
        h_s[r * 65 + c] = h[row0 * 64 + i];
    }
    __syncthreads();

    int g = tid >> 3, e = tid & 7;       // g: 0..15 -> rows 4g..4g+3
    float acc[4][8];
#pragma unroll
    for (int rr = 0; rr < 4; rr++)
#pragma unroll
        for (int i = 0; i < 8; i++) acc[rr][i] = 0.f;

#pragma unroll
    for (int k = 0; k < 64; k++) {
        float4 w0 = *(const float4*)&W_s[k * 64 + e * 4];
        float4 w1 = *(const float4*)&W_s[k * 64 + 32 + e * 4];
#pragma unroll
        for (int rr = 0; rr < 4; rr++) {
            float hv = h_s[(g * 4 + rr) * 65 + k];
            acc[rr][0] = fmaf(hv, w0.x, acc[rr][0]);
            acc[rr][1] = fmaf(hv, w0.y, acc[rr][1]);
            acc[rr][2] = fmaf(hv, w0.z, acc[rr][2]);
            acc[rr][3] = fmaf(hv, w0.w, acc[rr][3]);
            acc[rr][4] = fmaf(hv, w1.x, acc[rr][4]);
            acc[rr][5] = fmaf(hv, w1.y, acc[rr][5]);
            acc[rr][6] = fmaf(hv, w1.z, acc[rr][6]);
            acc[rr][7] = fmaf(hv, w1.w, acc[rr][7]);
        }
    }

#pragma unroll
    for (int rr = 0; rr < 4; rr++) {
        int row = row0 + g * 4 + rr;
        *(float4*)&g_Wh[(size_t)row * 64 + e * 4] =
            make_float4(acc[rr][0], acc[rr][1], acc[rr][2], acc[rr][3]);
        *(float4*)&g_Wh[(size_t)row * 64 + 32 + e * 4] =
            make_float4(acc[rr][4], acc[rr][5], acc[rr][6], acc[rr][7]);

        float ps = 0.f, pd = 0.f;
#pragma unroll
        for (int i = 0; i < 4; i++) {
            ps = fmaf(acc[rr][i], a_s[e * 4 + i], ps);
            ps = fmaf(acc[rr][i + 4], a_s[32 + e * 4 + i], ps);
            pd = fmaf(acc[rr][i], a_s[64 + e * 4 + i], pd);
            pd = fmaf(acc[rr][i + 4], a_s[96 + e * 4 + i], pd);
        }
#pragma unroll
        for (int o = 1; o < 8; o <<= 1) {
            ps += __shfl_xor_sync(0xffffffffu, ps, o);
            pd += __shfl_xor_sync(0xffffffffu, pd, o);
        }
        if (e == 0) {
            g_ssrc[row] = ps;
            g_suv[row] = make_float4(pd, expf(pd), expf(ALPHA * pd), 0.f);
        }
    }
}

// ---------------------------------------------------------------------------
// Kernel 2: per-batch max of s_dst.  Single block, warp per batch.
// ---------------------------------------------------------------------------
__global__ void __launch_bounds__(256) k2_max() {
    int w = threadIdx.x >> 5, lane = threadIdx.x & 31;
    float m = -1e30f;
    for (int j = lane; j < NTOK; j += 32) m = fmaxf(m, g_suv[w * NTOK + j].x);
#pragma unroll
    for (int o = 16; o > 0; o >>= 1)
        m = fmaxf(m, __shfl_xor_sync(0xffffffffu, m, o));
    if (lane == 0) g_maxs[w] = m;
}

// ---------------------------------------------------------------------------
// Kernel 3: fused attention, mma.sync tf32.
//   CTA 512 thr = 16 warps = 4 m-warps (32 rows each) x 4 j-split groups.
//   Per tile (128 j): stage Wh->smem (stride 72, tf32); js group handles 4 of
//   16 chunks; warp computes 2 m-tiles per chunk (B-frag LDS amortized 2x).
//   Software-pipelined staging (LDG t+1 in regs during compute of t).
//   Ones column (n-tile 8) -> Z.  3-round smem reduction over js, then elu.
// ---------------------------------------------------------------------------
#define SUV_BYTES  (NTOK * 16)
#define TS_BYTES   (128 * 73 * 4 + 256)   // holds 128x72 tile AND 128x73 red buf
#define SMEM3_TOTAL (SUV_BYTES + TS_BYTES)

__global__ void __launch_bounds__(512, 1) k3_attn(float* __restrict__ out) {
    extern __shared__ char smem[];
    float4* suv_s = (float4*)smem;               // [2048]
    float*  T_s   = (float*)(smem + SUV_BYTES);  // tile [128][72]; later red buf

    int tid = threadIdx.x;
    int lane = tid & 31;
    int wid = tid >> 5;
    int mw = wid & 3, js = wid >> 2;
    int b = blockIdx.y;
    int i0 = blockIdx.x * 128;

    // whole-batch suv into smem
    {
        const float4* sg = g_suv + b * NTOK;
        for (int i = tid; i < NTOK; i += 512) suv_s[i] = sg[i];
    }

    int q = lane >> 2, c4 = lane & 3;
    int rbase = i0 + mw * 32 + q;
    float M = g_maxs[b];
    float ssr[4], Ai[4], Bi[4];
#pragma unroll
    for (int rr = 0; rr < 4; rr++) {
        float s = g_ssrc[b * NTOK + rbase + rr * 8];
        float t = s + M;
        float m = t > 0.f ? t : ALPHA * t;
        ssr[rr] = s;
        Ai[rr] = expf(s - m);
        Bi[rr] = expf(ALPHA * s - m);
    }

    float acc[2][9][4];
#pragma unroll
    for (int mt = 0; mt < 2; mt++)
#pragma unroll
        for (int n = 0; n < 9; n++)
#pragma unroll
            for (int i = 0; i < 4; i++) acc[mt][n][i] = 0.f;

    const float4* WhG4 = (const float4*)(g_Wh + (size_t)b * NTOK * 64);
    int sj = (tid + 0) >> 4;        // staging row 0..127 (2048 idx / 16)
    // (each thread handles idx = tid + it*512)

    // ones column: rows x cols 64..71, col 64 = 1 (init once; staging never
    // touches cols >= 64, reduction happens after all MMAs)
    if (tid < 256) {
        int j = tid >> 1, hf = tid & 1;
        *(float4*)&T_s[j * 72 + 64 + hf * 4] =
            make_float4(hf ? 0.f : 1.f, 0.f, 0.f, 0.f);
    }

    // prefetch tile 0
    float4 pf[4];
#pragma unroll
    for (int it = 0; it < 4; it++) {
        int idx = tid + it * 512;
        pf[it] = WhG4[(size_t)((idx >> 4)) * 16 + (idx & 15)];
    }

    for (int t = 0; t < 16; t++) {
        // store prefetched tile (cvt to tf32)
#pragma unroll
        for (int it = 0; it < 4; it++) {
            int idx = tid + it * 512;
            int j = idx >> 4, o4 = idx & 15;
            float4 v = pf[it];
            v.x = __uint_as_float(cvt_tf32(v.x));
            v.y = __uint_as_float(cvt_tf32(v.y));
            v.z = __uint_as_float(cvt_tf32(v.z));
            v.w = __uint_as_float(cvt_tf32(v.w));
            *(float4*)&T_s[j * 72 + o4 * 4] = v;
        }
        __syncthreads();
        // prefetch next tile (overlaps with compute below)
        if (t < 15) {
#pragma unroll
            for (int it = 0; it < 4; it++) {
                int idx = tid + it * 512;
                pf[it] = WhG4[(size_t)((t + 1) * 128 + (idx >> 4)) * 16 + (idx & 15)];
            }
        }

#pragma unroll
        for (int cc = 0; cc < 4; cc++) {
            int c = js * 4 + cc;
            int jb = t * 128 + c * 8;
            float4 s0 = suv_s[jb + c4];
            float4 s1 = suv_s[jb + 4 + c4];
            uint32_t af[2][4];
#pragma unroll
            for (int mt = 0; mt < 2; mt++) {
                int r0 = mt * 2, r1 = mt * 2 + 1;
                float p0 = (ssr[r0] + s0.x > 0.f) ? Ai[r0] * s0.y : Bi[r0] * s0.z;
                float p1 = (ssr[r1] + s0.x > 0.f) ? Ai[r1] * s0.y : Bi[r1] * s0.z;
                float p2 = (ssr[r0] + s1.x > 0.f) ? Ai[r0] * s1.y : Bi[r0] * s1.z;
                float p3 = (ssr[r1] + s1.x > 0.f) ? Ai[r1] * s1.y : Bi[r1] * s1.z;
                af[mt][0] = cvt_tf32(p0);
                af[mt][1] = cvt_tf32(p1);
                af[mt][2] = cvt_tf32(p2);
                af[mt][3] = cvt_tf32(p3);
            }
            const float* bp = T_s + (c * 8 + c4) * 72 + q;
#pragma unroll
            for (int n = 0; n < 9; n++) {
                uint32_t b0 = __float_as_uint(bp[n * 8]);
                uint32_t b1 = __float_as_uint(bp[4 * 72 + n * 8]);
                mma_tf32(acc[0][n], af[0][0], af[0][1], af[0][2], af[0][3], b0, b1);
                mma_tf32(acc[1][n], af[1][0], af[1][1], af[1][2], af[1][3], b0, b1);
            }
        }
        __syncthreads();
    }

    // ---- reduce across js groups (stride-73 conflict-free smem buffer) ----
    float* accf = &acc[0][0][0];
    int slot = tid & 127;            // (mw, lane) identity
#pragma unroll
    for (int src = 1; src < 4; src++) {
        if (js == src) {
#pragma unroll
            for (int i = 0; i < 72; i++) T_s[slot * 73 + i] = accf[i];
        }
        __syncthreads();
        if (js == 0) {
#pragma unroll
            for (int i = 0; i < 72; i++) accf[i] += T_s[slot * 73 + i];
        }
        __syncthreads();
    }

    // ---- epilogue (js == 0 threads: tid < 128) ----
    if (js == 0) {
        float z0 = __shfl_sync(0xffffffffu, acc[0][8][0], (lane & 28));
        float z1 = __shfl_sync(0xffffffffu, acc[0][8][2], (lane & 28));
        float z2 = __shfl_sync(0xffffffffu, acc[1][8][0], (lane & 28));
        float z3 = __shfl_sync(0xffffffffu, acc[1][8][2], (lane & 28));
        float inv0 = 1.f / z0, inv1 = 1.f / z1;
        float inv2 = 1.f / z2, inv3 = 1.f / z3;

        float* o0 = out + ((size_t)(b * NTOK + rbase)) * 64 + 2 * c4;
        float* o1 = o0 + 8 * 64;
        float* o2 = o0 + 16 * 64;
        float* o3 = o0 + 24 * 64;
#pragma unroll
        for (int n = 0; n < 8; n++) {
            float2 w0, w1, w2, w3;
            w0.x = eluf(acc[0][n][0] * inv0);
            w0.y = eluf(acc[0][n][1] * inv0);
            w1.x = eluf(acc[0][n][2] * inv1);
            w1.y = eluf(acc[0][n][3] * inv1);
            w2.x = eluf(acc[1][n][0] * inv2);
            w2.y = eluf(acc[1][n][1] * inv2);
            w3.x = eluf(acc[1][n][2] * inv3);
            w3.y = eluf(acc[1][n][3] * inv3);
            *(float2*)(o0 + n * 8) = w0;
            *(float2*)(o1 + n * 8) = w1;
            *(float2*)(o2 + n * 8) = w2;
            *(float2*)(o3 + n * 8) = w3;
        }
    }
}

// ---------------------------------------------------------------------------
extern "C" void kernel_launch(void* const* d_in, const int* in_sizes, int n_in,
                              void* d_out, int out_size) {
    const float* h = (const float*)d_in[0];
    const float* W = (const float*)d_in[1];
    const float* a = (const float*)d_in[2];
    float* out = (float*)d_out;

    cudaFuncSetAttribute(k3_attn, cudaFuncAttributeMaxDynamicSharedMemorySize,
                         SMEM3_TOTAL);

    k1_proj<<<(BATCH * NTOK) / 64, 128>>>(h, W, a);
    k2_max<<<1, 256>>>();
    dim3 g3(NTOK / 128, BATCH);
    k3_attn<<<g3, 512, SMEM3_TOTAL>>>(out);
}